// round 1
// baseline (speedup 1.0000x reference)
#include <cuda_runtime.h>
#include <cuda_bf16.h>

// Problem constants (fixed by reference)
#define BB 2
#define LL 2048
#define DD 512
#define HH 8
#define EE 64
#define CC 128            // chunk length
#define NCH 16            // L / C
#define BHN 16            // B * H
#define MM 4096           // B * L

// ---------------- scratch (static device arrays; no allocation) ----------------
__device__ float g_qf[BB*HH*LL*EE];   // [B,H,L,E] feature-mapped q
__device__ float g_kf[BB*HH*LL*EE];
__device__ float g_vf[BB*HH*LL*EE];
__device__ float g_Sc [BHN*NCH*EE*EE]; // per-chunk kv summaries
__device__ float g_sc [BHN*NCH*EE];
__device__ float g_Sin[BHN*NCH*EE*EE]; // prefix state entering each chunk
__device__ float g_sin[BHN*NCH*EE];
__device__ float g_attn[MM*DD];        // attention output [B*L, D]
__device__ float g_proj[MM*DD];        // pre-layernorm projection

__device__ __forceinline__ float lam_of(const float* dl, int h) {
    return 0.99f + 0.01f / (1.0f + __expf(-dl[h]));
}

// ---------------- Kernel 1: QKV GEMM + bias + feature maps -------------------
// X [4096,512] @ W [512,1536], epilogue scatters into g_qf/g_kf/g_vf [B,H,L,E]
__global__ __launch_bounds__(256) void gemm_qkv_kernel(
    const float* __restrict__ X, const float* __restrict__ W,
    const float* __restrict__ bias)
{
    __shared__ float As[8][128];
    __shared__ float Bs[8][128];
    const int tid  = threadIdx.x;
    const int crow = blockIdx.y * 128;
    const int ccol = blockIdx.x * 128;
    const int aRow = tid >> 1, aCol = (tid & 1) << 2;
    const int bRow = tid >> 5, bCol = (tid & 31) << 2;
    const int tx = tid & 15, ty = tid >> 4;

    float acc[8][8];
#pragma unroll
    for (int i = 0; i < 8; i++)
#pragma unroll
        for (int j = 0; j < 8; j++) acc[i][j] = 0.f;

    for (int k0 = 0; k0 < 512; k0 += 8) {
        float4 a = *(const float4*)(X + (crow + aRow) * 512 + k0 + aCol);
        As[aCol+0][aRow] = a.x; As[aCol+1][aRow] = a.y;
        As[aCol+2][aRow] = a.z; As[aCol+3][aRow] = a.w;
        *(float4*)&Bs[bRow][bCol] =
            *(const float4*)(W + (k0 + bRow) * 1536 + ccol + bCol);
        __syncthreads();
#pragma unroll
        for (int kk = 0; kk < 8; kk++) {
            float ra[8], rb[8];
#pragma unroll
            for (int i = 0; i < 8; i++) ra[i] = As[kk][ty*8+i];
#pragma unroll
            for (int j = 0; j < 8; j++) rb[j] = Bs[kk][tx*8+j];
#pragma unroll
            for (int i = 0; i < 8; i++)
#pragma unroll
                for (int j = 0; j < 8; j++) acc[i][j] += ra[i]*rb[j];
        }
        __syncthreads();
    }

#pragma unroll
    for (int i = 0; i < 8; i++) {
#pragma unroll
        for (int j = 0; j < 8; j++) {
            int m = crow + ty*8 + i;
            int n = ccol + tx*8 + j;
            float val = acc[i][j] + bias[n];
            int kind = n >> 9, d = n & 511;
            int h = d >> 6, e = d & 63;
            int bb = m >> 11, l = m & 2047;
            int idx = (((bb<<3) + h) * 2048 + l) * 64 + e;
            if (kind == 0)
                g_qf[idx] = (val > 0.f ? val + 1.f : __expf(val)) * 0.125f;
            else if (kind == 1)
                g_kf[idx] = (val > 0.f ? val + 1.f : __expf(val));
            else
                g_vf[idx] = val;
        }
    }
}

// ---------------- Kernel 2: per-chunk kv summaries ---------------------------
// Sc[e][f] = sum_t lam^(C-1-t) k[t][e] v[t][f];  sc[e] = sum_t lam^(C-1-t) k[t][e]
__global__ __launch_bounds__(256) void chunk_sum_kernel(const float* __restrict__ dl)
{
    extern __shared__ float sm[];
    float* ks   = sm;                 // 128*65
    float* vs   = ks + 128*65;        // 128*65
    float* lamp = vs + 128*65;        // 129
    const int tid = threadIdx.x;
    const int chunk = blockIdx.x, bh = blockIdx.y;
    const int h = bh & 7;
    float lam = lam_of(dl, h);
    float logl = __logf(lam);
    if (tid <= 128) lamp[tid] = __expf((float)tid * logl);

    const float* kg = g_kf + (bh * LL + chunk * CC) * EE;
    const float* vg = g_vf + (bh * LL + chunk * CC) * EE;
    for (int idx = tid; idx < CC*EE; idx += 256) {
        int r = idx >> 6, e = idx & 63;
        ks[r*65+e] = kg[idx];
        vs[r*65+e] = vg[idx];
    }
    __syncthreads();

    const int e0 = (tid >> 4) << 2, f0 = (tid & 15) << 2;
    float acc[4][4];
#pragma unroll
    for (int i = 0; i < 4; i++)
#pragma unroll
        for (int j = 0; j < 4; j++) acc[i][j] = 0.f;

    for (int t = 0; t < CC; t++) {
        float w = lamp[CC-1-t];
        float rk[4], rv[4];
#pragma unroll
        for (int i = 0; i < 4; i++) rk[i] = ks[t*65+e0+i] * w;
#pragma unroll
        for (int j = 0; j < 4; j++) rv[j] = vs[t*65+f0+j];
#pragma unroll
        for (int i = 0; i < 4; i++)
#pragma unroll
            for (int j = 0; j < 4; j++) acc[i][j] += rk[i]*rv[j];
    }
    float* Sc = g_Sc + (bh*NCH + chunk) * EE*EE;
#pragma unroll
    for (int i = 0; i < 4; i++)
#pragma unroll
        for (int j = 0; j < 4; j++) Sc[(e0+i)*EE + f0+j] = acc[i][j];

    if (tid < EE) {
        float s = 0.f;
        for (int t = 0; t < CC; t++) s += lamp[CC-1-t] * ks[t*65+tid];
        g_sc[(bh*NCH + chunk)*EE + tid] = s;
    }
}

// ---------------- Kernel 3: inter-chunk scan (tiny) --------------------------
__global__ __launch_bounds__(256) void scan_kernel(const float* __restrict__ dl)
{
    const int bh = blockIdx.x, tid = threadIdx.x;
    const int h = bh & 7;
    float lam = lam_of(dl, h);
    float lamC = __expf((float)CC * __logf(lam));

    for (int idx = tid; idx < EE*EE; idx += 256) {
        float vals[NCH];
#pragma unroll
        for (int c = 0; c < NCH; c++) vals[c] = g_Sc[(bh*NCH+c)*EE*EE + idx];
        float run = 0.f;
#pragma unroll
        for (int c = 0; c < NCH; c++) {
            g_Sin[(bh*NCH+c)*EE*EE + idx] = run;
            run = lamC*run + vals[c];
        }
    }
    if (tid < EE) {
        float vals[NCH];
#pragma unroll
        for (int c = 0; c < NCH; c++) vals[c] = g_sc[(bh*NCH+c)*EE + tid];
        float run = 0.f;
#pragma unroll
        for (int c = 0; c < NCH; c++) {
            g_sin[(bh*NCH+c)*EE + tid] = run;
            run = lamC*run + vals[c];
        }
    }
}

// ---------------- Kernel 4: intra-chunk attention + output -------------------
__global__ __launch_bounds__(256) void attn_chunk_kernel(const float* __restrict__ dl)
{
    extern __shared__ float sm[];
    float* qs    = sm;                  // 128*65
    float* ks    = qs + 8320;           // 128*65
    float* vs    = ks + 8320;           // 128*65
    float* Asm   = vs + 8320;           // 128*132
    float* Sin   = Asm + 128*132;       // 64*65
    float* sinv  = Sin + 64*65;         // 64
    float* lamp  = sinv + 64;           // 129
    float* den   = lamp + 129;          // 128

    const int tid = threadIdx.x;
    const int chunk = blockIdx.x, bh = blockIdx.y;
    const int h = bh & 7;
    float lam = lam_of(dl, h);
    float logl = __logf(lam);
    if (tid <= 128) lamp[tid] = __expf((float)tid * logl);

    const int base = (bh * LL + chunk * CC) * EE;
    for (int idx = tid; idx < CC*EE; idx += 256) {
        int r = idx >> 6, e = idx & 63;
        qs[r*65+e] = g_qf[base+idx];
        ks[r*65+e] = g_kf[base+idx];
        vs[r*65+e] = g_vf[base+idx];
    }
    const float* gS = g_Sin + (bh*NCH + chunk) * EE*EE;
    for (int idx = tid; idx < EE*EE; idx += 256)
        Sin[(idx>>6)*65 + (idx&63)] = gS[idx];
    if (tid < EE) sinv[tid] = g_sin[(bh*NCH + chunk)*EE + tid];
    __syncthreads();

    // Step 1: A = Q K^T, masked lower-triangular with lam^(t-j)
    {
        const int tx = tid & 15, ty = tid >> 4;
        const int t0 = ty*8, j0 = tx*8;
        float a[8][8];
#pragma unroll
        for (int i = 0; i < 8; i++)
#pragma unroll
            for (int j = 0; j < 8; j++) a[i][j] = 0.f;
        for (int e = 0; e < EE; e++) {
            float rq[8], rk[8];
#pragma unroll
            for (int i = 0; i < 8; i++) rq[i] = qs[(t0+i)*65 + e];
#pragma unroll
            for (int j = 0; j < 8; j++) rk[j] = ks[(j0+j)*65 + e];
#pragma unroll
            for (int i = 0; i < 8; i++)
#pragma unroll
                for (int j = 0; j < 8; j++) a[i][j] += rq[i]*rk[j];
        }
#pragma unroll
        for (int i = 0; i < 8; i++)
#pragma unroll
            for (int j = 0; j < 8; j++) {
                int t = t0+i, jj = j0+j;
                Asm[t*132+jj] = (jj <= t) ? a[i][j]*lamp[t-jj] : 0.f;
            }
    }
    __syncthreads();

    // Step 2: denominators
    if (tid < CC) {
        int t = tid;
        float s = 0.f;
        for (int j = 0; j <= t; j++) s += Asm[t*132+j];
        float qd = 0.f;
#pragma unroll
        for (int e = 0; e < EE; e++) qd += qs[t*65+e] * sinv[e];
        den[t] = s + lamp[t+1]*qd + 1e-6f;
    }

    // Step 3: O = A@V + lam^(t+1) * Q @ Sin  (den written before the sync below)
    const int f0 = (tid & 15) << 2;
    const int t0 = (tid >> 4) * 8;
    float o[8][4], oi[8][4];
#pragma unroll
    for (int i = 0; i < 8; i++)
#pragma unroll
        for (int j = 0; j < 4; j++) { o[i][j] = 0.f; oi[i][j] = 0.f; }

    for (int j = 0; j < CC; j++) {
        float rv[4];
#pragma unroll
        for (int jj = 0; jj < 4; jj++) rv[jj] = vs[j*65+f0+jj];
#pragma unroll
        for (int i = 0; i < 8; i++) {
            float ra = Asm[(t0+i)*132+j];
#pragma unroll
            for (int jj = 0; jj < 4; jj++) o[i][jj] += ra*rv[jj];
        }
    }
    for (int e = 0; e < EE; e++) {
        float rs[4];
#pragma unroll
        for (int jj = 0; jj < 4; jj++) rs[jj] = Sin[e*65+f0+jj];
#pragma unroll
        for (int i = 0; i < 8; i++) {
            float rq = qs[(t0+i)*65+e];
#pragma unroll
            for (int jj = 0; jj < 4; jj++) oi[i][jj] += rq*rs[jj];
        }
    }
    __syncthreads();   // den visible

    const int b = bh >> 3;
#pragma unroll
    for (int i = 0; i < 8; i++) {
        int t = t0 + i;
        float inv = 1.0f / den[t];
        float lp = lamp[t+1];
        int row = b*LL + chunk*CC + t;
        int col = h*EE + f0;
#pragma unroll
        for (int jj = 0; jj < 4; jj++)
            g_attn[row*DD + col + jj] = (o[i][jj] + lp*oi[i][jj]) * inv;
    }
}

// ---------------- Kernel 5: output projection GEMM ---------------------------
__global__ __launch_bounds__(256) void gemm_out_kernel(
    const float* __restrict__ W, const float* __restrict__ bias)
{
    __shared__ float As[8][128];
    __shared__ float Bs[8][128];
    const int tid  = threadIdx.x;
    const int crow = blockIdx.y * 128;
    const int ccol = blockIdx.x * 128;
    const int aRow = tid >> 1, aCol = (tid & 1) << 2;
    const int bRow = tid >> 5, bCol = (tid & 31) << 2;
    const int tx = tid & 15, ty = tid >> 4;

    float acc[8][8];
#pragma unroll
    for (int i = 0; i < 8; i++)
#pragma unroll
        for (int j = 0; j < 8; j++) acc[i][j] = 0.f;

    for (int k0 = 0; k0 < 512; k0 += 8) {
        float4 a = *(const float4*)(g_attn + (crow + aRow) * 512 + k0 + aCol);
        As[aCol+0][aRow] = a.x; As[aCol+1][aRow] = a.y;
        As[aCol+2][aRow] = a.z; As[aCol+3][aRow] = a.w;
        *(float4*)&Bs[bRow][bCol] =
            *(const float4*)(W + (k0 + bRow) * 512 + ccol + bCol);
        __syncthreads();
#pragma unroll
        for (int kk = 0; kk < 8; kk++) {
            float ra[8], rb[8];
#pragma unroll
            for (int i = 0; i < 8; i++) ra[i] = As[kk][ty*8+i];
#pragma unroll
            for (int j = 0; j < 8; j++) rb[j] = Bs[kk][tx*8+j];
#pragma unroll
            for (int i = 0; i < 8; i++)
#pragma unroll
                for (int j = 0; j < 8; j++) acc[i][j] += ra[i]*rb[j];
        }
        __syncthreads();
    }
#pragma unroll
    for (int i = 0; i < 8; i++)
#pragma unroll
        for (int j = 0; j < 8; j++) {
            int m = crow + ty*8 + i;
            int n = ccol + tx*8 + j;
            g_proj[m*512 + n] = acc[i][j] + bias[n];
        }
}

// ---------------- Kernel 6: LayerNorm ----------------------------------------
__global__ __launch_bounds__(128) void ln_kernel(
    const float* __restrict__ g, const float* __restrict__ b,
    float* __restrict__ out)
{
    const int row = blockIdx.x;
    const int tid = threadIdx.x;
    const float4 v = reinterpret_cast<const float4*>(g_proj + row*512)[tid];
    float s  = v.x + v.y + v.z + v.w;
    float sq = v.x*v.x + v.y*v.y + v.z*v.z + v.w*v.w;
#pragma unroll
    for (int o = 16; o; o >>= 1) {
        s  += __shfl_xor_sync(0xffffffffu, s,  o);
        sq += __shfl_xor_sync(0xffffffffu, sq, o);
    }
    __shared__ float ss[4], ssq[4];
    if ((tid & 31) == 0) { ss[tid>>5] = s; ssq[tid>>5] = sq; }
    __syncthreads();
    s  = ss[0] + ss[1] + ss[2] + ss[3];
    sq = ssq[0] + ssq[1] + ssq[2] + ssq[3];
    const float mu = s * (1.0f/512.0f);
    const float var = sq * (1.0f/512.0f) - mu*mu;
    const float rstd = rsqrtf(var + 1e-5f);
    const float4 gg = reinterpret_cast<const float4*>(g)[tid];
    const float4 bb = reinterpret_cast<const float4*>(b)[tid];
    float4 r;
    r.x = (v.x - mu)*rstd*gg.x + bb.x;
    r.y = (v.y - mu)*rstd*gg.y + bb.y;
    r.z = (v.z - mu)*rstd*gg.z + bb.z;
    r.w = (v.w - mu)*rstd*gg.w + bb.w;
    reinterpret_cast<float4*>(out + row*512)[tid] = r;
}

// ---------------- launch ------------------------------------------------------
extern "C" void kernel_launch(void* const* d_in, const int* in_sizes, int n_in,
                              void* d_out, int out_size)
{
    const float* x    = (const float*)d_in[0];
    const float* Wqkv = (const float*)d_in[1];
    const float* bqkv = (const float*)d_in[2];
    const float* Wout = (const float*)d_in[3];
    const float* bout = (const float*)d_in[4];
    const float* dl   = (const float*)d_in[5];
    const float* lng  = (const float*)d_in[6];
    const float* lnb  = (const float*)d_in[7];
    float* out = (float*)d_out;

    const size_t smem2 = (size_t)(2*128*65 + 129) * sizeof(float);
    const size_t smem4 = (size_t)(3*8320 + 128*132 + 64*65 + 64 + 129 + 128) * sizeof(float);
    cudaFuncSetAttribute(chunk_sum_kernel,
        cudaFuncAttributeMaxDynamicSharedMemorySize, (int)smem2);
    cudaFuncSetAttribute(attn_chunk_kernel,
        cudaFuncAttributeMaxDynamicSharedMemorySize, (int)smem4);

    gemm_qkv_kernel<<<dim3(12, 32), 256>>>(x, Wqkv, bqkv);
    chunk_sum_kernel<<<dim3(NCH, BHN), 256, smem2>>>(dl);
    scan_kernel<<<BHN, 256>>>(dl);
    attn_chunk_kernel<<<dim3(NCH, BHN), 256, smem4>>>(dl);
    gemm_out_kernel<<<dim3(4, 32), 256>>>(Wout, bout);
    ln_kernel<<<MM, 128>>>(lng, lnb, out);
}

// round 5
// speedup vs baseline: 1.5673x; 1.5673x over previous
#include <cuda_runtime.h>
#include <cuda_bf16.h>
#include <mma.h>

using namespace nvcuda;

// Problem constants (fixed by reference)
#define BB 2
#define LL 2048
#define DD 512
#define HH 8
#define EE 64
#define CC 128            // chunk length
#define NCH 16            // L / C
#define BHN 16            // B * H
#define MM 4096           // B * L

// ---------------- scratch (static device arrays; no allocation) ----------------
__device__ float g_qf[BB*HH*LL*EE];   // [B,H,L,E] feature-mapped q
__device__ float g_kf[BB*HH*LL*EE];
__device__ float g_vf[BB*HH*LL*EE];
__device__ float g_Sc [BHN*NCH*EE*EE]; // per-chunk kv summaries
__device__ float g_sc [BHN*NCH*EE];
__device__ float g_Sin[BHN*NCH*EE*EE]; // prefix state entering each chunk
__device__ float g_sin[BHN*NCH*EE];
__device__ float g_attn[MM*DD];        // attention output [B*L, D]
__device__ float g_proj[MM*DD];        // pre-layernorm projection

__device__ __forceinline__ float lam_of(const float* dl, int h) {
    return 0.99f + 0.01f / (1.0f + __expf(-dl[h]));
}

// split fp32 -> bf16 hi + bf16 lo (x ~= hi + lo, residual <= 2^-18 rel)
__device__ __forceinline__ void split_store4(
    __nv_bfloat16* __restrict__ ph, __nv_bfloat16* __restrict__ pl, float4 v)
{
    float vs[4] = {v.x, v.y, v.z, v.w};
#pragma unroll
    for (int i = 0; i < 4; i++) {
        __nv_bfloat16 h = __float2bfloat16(vs[i]);
        ph[i] = h;
        pl[i] = __float2bfloat16(vs[i] - __bfloat162float(h));
    }
}

// Strides padded so every 16x16 fragment base is 32-byte aligned:
// AH_LD*2B = 96B, BH_LD*2B = 288B (both multiples of 32).
#define AH_LD 48
#define BH_LD 144

// ---------------- Kernel 1: QKV GEMM (bf16x3 tensor-core) + feature maps -----
// X [4096,512] @ W [512,1536]; epilogue scatters into g_qf/g_kf/g_vf [B,H,L,E]
// Block tile 128x128, 8 warps (4 along M x 2 along N), warp tile 32x64.
__global__ __launch_bounds__(256) void gemm_qkv_kernel(
    const float* __restrict__ X, const float* __restrict__ W,
    const float* __restrict__ bias)
{
    extern __shared__ __align__(128) char smem_raw[];
    __nv_bfloat16* Ah = (__nv_bfloat16*)smem_raw;        // 128*AH_LD
    __nv_bfloat16* Al = Ah + 128*AH_LD;
    __nv_bfloat16* Bh = Al + 128*AH_LD;                  // 32*BH_LD
    __nv_bfloat16* Bl = Bh + 32*BH_LD;
    float* Cs = (float*)(Bl + 32*BH_LD);                 // 8 warps * 32*64

    const int tid  = threadIdx.x;
    const int warpId = tid >> 5;
    const int lane   = tid & 31;
    const int wm = warpId & 3;    // 0..3  (M)
    const int wn = warpId >> 2;   // 0..1  (N)
    const int crow = blockIdx.y * 128;
    const int ccol = blockIdx.x * 128;

    wmma::fragment<wmma::accumulator,16,16,16,float> acc[2][4];
#pragma unroll
    for (int i = 0; i < 2; i++)
#pragma unroll
        for (int j = 0; j < 4; j++) wmma::fill_fragment(acc[i][j], 0.0f);

    for (int kt = 0; kt < 512; kt += 32) {
        // load A tile 128x32 (1024 float4)
#pragma unroll
        for (int t = 0; t < 4; t++) {
            int f4 = tid + t*256;
            int row = f4 >> 3, c = (f4 & 7) << 2;
            float4 a = *(const float4*)(X + (crow+row)*512 + kt + c);
            split_store4(Ah + row*AH_LD + c, Al + row*AH_LD + c, a);
        }
        // load B tile 32x128 (1024 float4)
#pragma unroll
        for (int t = 0; t < 4; t++) {
            int f4 = tid + t*256;
            int row = f4 >> 5, c = (f4 & 31) << 2;
            float4 b = *(const float4*)(W + (kt+row)*1536 + ccol + c);
            split_store4(Bh + row*BH_LD + c, Bl + row*BH_LD + c, b);
        }
        __syncthreads();

#pragma unroll
        for (int kk = 0; kk < 32; kk += 16) {
            wmma::fragment<wmma::matrix_a,16,16,16,__nv_bfloat16,wmma::row_major> ah[2], al[2];
            wmma::fragment<wmma::matrix_b,16,16,16,__nv_bfloat16,wmma::row_major> bh[4], bl[4];
#pragma unroll
            for (int i = 0; i < 2; i++) {
                wmma::load_matrix_sync(ah[i], Ah + (wm*32 + i*16)*AH_LD + kk, AH_LD);
                wmma::load_matrix_sync(al[i], Al + (wm*32 + i*16)*AH_LD + kk, AH_LD);
            }
#pragma unroll
            for (int j = 0; j < 4; j++) {
                wmma::load_matrix_sync(bh[j], Bh + kk*BH_LD + wn*64 + j*16, BH_LD);
                wmma::load_matrix_sync(bl[j], Bl + kk*BH_LD + wn*64 + j*16, BH_LD);
            }
#pragma unroll
            for (int i = 0; i < 2; i++)
#pragma unroll
                for (int j = 0; j < 4; j++) {
                    wmma::mma_sync(acc[i][j], ah[i], bh[j], acc[i][j]);
                    wmma::mma_sync(acc[i][j], ah[i], bl[j], acc[i][j]);
                    wmma::mma_sync(acc[i][j], al[i], bh[j], acc[i][j]);
                }
        }
        __syncthreads();
    }

    // epilogue: stage per-warp 32x64 tile, apply bias + feature maps, scatter
    float* cw = Cs + warpId * (32*64);
#pragma unroll
    for (int i = 0; i < 2; i++)
#pragma unroll
        for (int j = 0; j < 4; j++)
            wmma::store_matrix_sync(cw + i*16*64 + j*16, acc[i][j], 64, wmma::mem_row_major);
    __syncwarp();

    const int n0 = ccol + wn*64 + lane*2;   // each lane: 2 consecutive cols
    const float b0 = bias[n0], b1 = bias[n0+1];
#pragma unroll 4
    for (int r = 0; r < 32; r++) {
        int m = crow + wm*32 + r;
        float2 v = *(float2*)(cw + r*64 + lane*2);
        float vals[2] = {v.x + b0, v.y + b1};
#pragma unroll
        for (int s = 0; s < 2; s++) {
            int n = n0 + s;
            float val = vals[s];
            int kind = n >> 9, d = n & 511;
            int h = d >> 6, e = d & 63;
            int bb = m >> 11, l = m & 2047;
            int idx = (((bb<<3) + h) * 2048 + l) * 64 + e;
            if (kind == 0)
                g_qf[idx] = (val > 0.f ? val + 1.f : __expf(val)) * 0.125f;
            else if (kind == 1)
                g_kf[idx] = (val > 0.f ? val + 1.f : __expf(val));
            else
                g_vf[idx] = val;
        }
    }
}

// ---------------- Kernel 5: output projection GEMM (bf16x3 tensor-core) ------
__global__ __launch_bounds__(256) void gemm_out_kernel(
    const float* __restrict__ W, const float* __restrict__ bias)
{
    extern __shared__ __align__(128) char smem_raw[];
    __nv_bfloat16* Ah = (__nv_bfloat16*)smem_raw;
    __nv_bfloat16* Al = Ah + 128*AH_LD;
    __nv_bfloat16* Bh = Al + 128*AH_LD;
    __nv_bfloat16* Bl = Bh + 32*BH_LD;
    float* Cs = (float*)(Bl + 32*BH_LD);

    const int tid  = threadIdx.x;
    const int warpId = tid >> 5;
    const int lane   = tid & 31;
    const int wm = warpId & 3;
    const int wn = warpId >> 2;
    const int crow = blockIdx.y * 128;
    const int ccol = blockIdx.x * 128;

    wmma::fragment<wmma::accumulator,16,16,16,float> acc[2][4];
#pragma unroll
    for (int i = 0; i < 2; i++)
#pragma unroll
        for (int j = 0; j < 4; j++) wmma::fill_fragment(acc[i][j], 0.0f);

    for (int kt = 0; kt < 512; kt += 32) {
#pragma unroll
        for (int t = 0; t < 4; t++) {
            int f4 = tid + t*256;
            int row = f4 >> 3, c = (f4 & 7) << 2;
            float4 a = *(const float4*)(g_attn + (crow+row)*512 + kt + c);
            split_store4(Ah + row*AH_LD + c, Al + row*AH_LD + c, a);
        }
#pragma unroll
        for (int t = 0; t < 4; t++) {
            int f4 = tid + t*256;
            int row = f4 >> 5, c = (f4 & 31) << 2;
            float4 b = *(const float4*)(W + (kt+row)*512 + ccol + c);
            split_store4(Bh + row*BH_LD + c, Bl + row*BH_LD + c, b);
        }
        __syncthreads();

#pragma unroll
        for (int kk = 0; kk < 32; kk += 16) {
            wmma::fragment<wmma::matrix_a,16,16,16,__nv_bfloat16,wmma::row_major> ah[2], al[2];
            wmma::fragment<wmma::matrix_b,16,16,16,__nv_bfloat16,wmma::row_major> bh[4], bl[4];
#pragma unroll
            for (int i = 0; i < 2; i++) {
                wmma::load_matrix_sync(ah[i], Ah + (wm*32 + i*16)*AH_LD + kk, AH_LD);
                wmma::load_matrix_sync(al[i], Al + (wm*32 + i*16)*AH_LD + kk, AH_LD);
            }
#pragma unroll
            for (int j = 0; j < 4; j++) {
                wmma::load_matrix_sync(bh[j], Bh + kk*BH_LD + wn*64 + j*16, BH_LD);
                wmma::load_matrix_sync(bl[j], Bl + kk*BH_LD + wn*64 + j*16, BH_LD);
            }
#pragma unroll
            for (int i = 0; i < 2; i++)
#pragma unroll
                for (int j = 0; j < 4; j++) {
                    wmma::mma_sync(acc[i][j], ah[i], bh[j], acc[i][j]);
                    wmma::mma_sync(acc[i][j], ah[i], bl[j], acc[i][j]);
                    wmma::mma_sync(acc[i][j], al[i], bh[j], acc[i][j]);
                }
        }
        __syncthreads();
    }

    float* cw = Cs + warpId * (32*64);
#pragma unroll
    for (int i = 0; i < 2; i++)
#pragma unroll
        for (int j = 0; j < 4; j++)
            wmma::store_matrix_sync(cw + i*16*64 + j*16, acc[i][j], 64, wmma::mem_row_major);
    __syncwarp();

    const int n0 = ccol + wn*64 + lane*2;
    const float b0 = bias[n0], b1 = bias[n0+1];
#pragma unroll 4
    for (int r = 0; r < 32; r++) {
        int m = crow + wm*32 + r;
        float2 v = *(float2*)(cw + r*64 + lane*2);
        float2 o; o.x = v.x + b0; o.y = v.y + b1;
        *(float2*)(g_proj + m*512 + n0) = o;
    }
}

// ---------------- Kernel 2: per-chunk kv summaries ---------------------------
__global__ __launch_bounds__(256) void chunk_sum_kernel(const float* __restrict__ dl)
{
    extern __shared__ float sm[];
    float* ks   = sm;                 // 128*65
    float* vs   = ks + 128*65;        // 128*65
    float* lamp = vs + 128*65;        // 129
    const int tid = threadIdx.x;
    const int chunk = blockIdx.x, bh = blockIdx.y;
    const int h = bh & 7;
    float lam = lam_of(dl, h);
    float logl = __logf(lam);
    if (tid <= 128) lamp[tid] = __expf((float)tid * logl);

    const float* kg = g_kf + (bh * LL + chunk * CC) * EE;
    const float* vg = g_vf + (bh * LL + chunk * CC) * EE;
    for (int idx = tid; idx < CC*EE; idx += 256) {
        int r = idx >> 6, e = idx & 63;
        ks[r*65+e] = kg[idx];
        vs[r*65+e] = vg[idx];
    }
    __syncthreads();

    const int e0 = (tid >> 4) << 2, f0 = (tid & 15) << 2;
    float acc[4][4];
#pragma unroll
    for (int i = 0; i < 4; i++)
#pragma unroll
        for (int j = 0; j < 4; j++) acc[i][j] = 0.f;

    for (int t = 0; t < CC; t++) {
        float w = lamp[CC-1-t];
        float rk[4], rv[4];
#pragma unroll
        for (int i = 0; i < 4; i++) rk[i] = ks[t*65+e0+i] * w;
#pragma unroll
        for (int j = 0; j < 4; j++) rv[j] = vs[t*65+f0+j];
#pragma unroll
        for (int i = 0; i < 4; i++)
#pragma unroll
            for (int j = 0; j < 4; j++) acc[i][j] += rk[i]*rv[j];
    }
    float* Sc = g_Sc + (bh*NCH + chunk) * EE*EE;
#pragma unroll
    for (int i = 0; i < 4; i++)
#pragma unroll
        for (int j = 0; j < 4; j++) Sc[(e0+i)*EE + f0+j] = acc[i][j];

    if (tid < EE) {
        float s = 0.f;
        for (int t = 0; t < CC; t++) s += lamp[CC-1-t] * ks[t*65+tid];
        g_sc[(bh*NCH + chunk)*EE + tid] = s;
    }
}

// ---------------- Kernel 3: inter-chunk scan (tiny) --------------------------
__global__ __launch_bounds__(256) void scan_kernel(const float* __restrict__ dl)
{
    const int bh = blockIdx.x, tid = threadIdx.x;
    const int h = bh & 7;
    float lam = lam_of(dl, h);
    float lamC = __expf((float)CC * __logf(lam));

    for (int idx = tid; idx < EE*EE; idx += 256) {
        float vals[NCH];
#pragma unroll
        for (int c = 0; c < NCH; c++) vals[c] = g_Sc[(bh*NCH+c)*EE*EE + idx];
        float run = 0.f;
#pragma unroll
        for (int c = 0; c < NCH; c++) {
            g_Sin[(bh*NCH+c)*EE*EE + idx] = run;
            run = lamC*run + vals[c];
        }
    }
    if (tid < EE) {
        float vals[NCH];
#pragma unroll
        for (int c = 0; c < NCH; c++) vals[c] = g_sc[(bh*NCH+c)*EE + tid];
        float run = 0.f;
#pragma unroll
        for (int c = 0; c < NCH; c++) {
            g_sin[(bh*NCH+c)*EE + tid] = run;
            run = lamC*run + vals[c];
        }
    }
}

// ---------------- Kernel 4: intra-chunk attention + output -------------------
__global__ __launch_bounds__(256) void attn_chunk_kernel(const float* __restrict__ dl)
{
    extern __shared__ float sm[];
    float* qs    = sm;                  // 128*65
    float* ks    = qs + 8320;           // 128*65
    float* vs    = ks + 8320;           // 128*65
    float* Asm   = vs + 8320;           // 128*132
    float* Sin   = Asm + 128*132;       // 64*65
    float* sinv  = Sin + 64*65;         // 64
    float* lamp  = sinv + 64;           // 129
    float* den   = lamp + 129;          // 128

    const int tid = threadIdx.x;
    const int chunk = blockIdx.x, bh = blockIdx.y;
    const int h = bh & 7;
    float lam = lam_of(dl, h);
    float logl = __logf(lam);
    if (tid <= 128) lamp[tid] = __expf((float)tid * logl);

    const int base = (bh * LL + chunk * CC) * EE;
    for (int idx = tid; idx < CC*EE; idx += 256) {
        int r = idx >> 6, e = idx & 63;
        qs[r*65+e] = g_qf[base+idx];
        ks[r*65+e] = g_kf[base+idx];
        vs[r*65+e] = g_vf[base+idx];
    }
    const float* gS = g_Sin + (bh*NCH + chunk) * EE*EE;
    for (int idx = tid; idx < EE*EE; idx += 256)
        Sin[(idx>>6)*65 + (idx&63)] = gS[idx];
    if (tid < EE) sinv[tid] = g_sin[(bh*NCH + chunk)*EE + tid];
    __syncthreads();

    // Step 1: A = Q K^T, masked lower-triangular with lam^(t-j)
    {
        const int tx = tid & 15, ty = tid >> 4;
        const int t0 = ty*8, j0 = tx*8;
        float a[8][8];
#pragma unroll
        for (int i = 0; i < 8; i++)
#pragma unroll
            for (int j = 0; j < 8; j++) a[i][j] = 0.f;
        for (int e = 0; e < EE; e++) {
            float rq[8], rk[8];
#pragma unroll
            for (int i = 0; i < 8; i++) rq[i] = qs[(t0+i)*65 + e];
#pragma unroll
            for (int j = 0; j < 8; j++) rk[j] = ks[(j0+j)*65 + e];
#pragma unroll
            for (int i = 0; i < 8; i++)
#pragma unroll
                for (int j = 0; j < 8; j++) a[i][j] += rq[i]*rk[j];
        }
#pragma unroll
        for (int i = 0; i < 8; i++)
#pragma unroll
            for (int j = 0; j < 8; j++) {
                int t = t0+i, jj = j0+j;
                Asm[t*132+jj] = (jj <= t) ? a[i][j]*lamp[t-jj] : 0.f;
            }
    }
    __syncthreads();

    // Step 2: denominators
    if (tid < CC) {
        int t = tid;
        float s = 0.f;
        for (int j = 0; j <= t; j++) s += Asm[t*132+j];
        float qd = 0.f;
#pragma unroll
        for (int e = 0; e < EE; e++) qd += qs[t*65+e] * sinv[e];
        den[t] = s + lamp[t+1]*qd + 1e-6f;
    }

    // Step 3: O = A@V + lam^(t+1) * Q @ Sin
    const int f0 = (tid & 15) << 2;
    const int t0 = (tid >> 4) * 8;
    float o[8][4], oi[8][4];
#pragma unroll
    for (int i = 0; i < 8; i++)
#pragma unroll
        for (int j = 0; j < 4; j++) { o[i][j] = 0.f; oi[i][j] = 0.f; }

    for (int j = 0; j < CC; j++) {
        float rv[4];
#pragma unroll
        for (int jj = 0; jj < 4; jj++) rv[jj] = vs[j*65+f0+jj];
#pragma unroll
        for (int i = 0; i < 8; i++) {
            float ra = Asm[(t0+i)*132+j];
#pragma unroll
            for (int jj = 0; jj < 4; jj++) o[i][jj] += ra*rv[jj];
        }
    }
    for (int e = 0; e < EE; e++) {
        float rs[4];
#pragma unroll
        for (int jj = 0; jj < 4; jj++) rs[jj] = Sin[e*65+f0+jj];
#pragma unroll
        for (int i = 0; i < 8; i++) {
            float rq = qs[(t0+i)*65+e];
#pragma unroll
            for (int jj = 0; jj < 4; jj++) oi[i][jj] += rq*rs[jj];
        }
    }
    __syncthreads();   // den visible

    const int b = bh >> 3;
#pragma unroll
    for (int i = 0; i < 8; i++) {
        int t = t0 + i;
        float inv = 1.0f / den[t];
        float lp = lamp[t+1];
        int row = b*LL + chunk*CC + t;
        int col = h*EE + f0;
#pragma unroll
        for (int jj = 0; jj < 4; jj++)
            g_attn[row*DD + col + jj] = (o[i][jj] + lp*oi[i][jj]) * inv;
    }
}

// ---------------- Kernel 6: LayerNorm ----------------------------------------
__global__ __launch_bounds__(128) void ln_kernel(
    const float* __restrict__ g, const float* __restrict__ b,
    float* __restrict__ out)
{
    const int row = blockIdx.x;
    const int tid = threadIdx.x;
    const float4 v = reinterpret_cast<const float4*>(g_proj + row*512)[tid];
    float s  = v.x + v.y + v.z + v.w;
    float sq = v.x*v.x + v.y*v.y + v.z*v.z + v.w*v.w;
#pragma unroll
    for (int o = 16; o; o >>= 1) {
        s  += __shfl_xor_sync(0xffffffffu, s,  o);
        sq += __shfl_xor_sync(0xffffffffu, sq, o);
    }
    __shared__ float ss[4], ssq[4];
    if ((tid & 31) == 0) { ss[tid>>5] = s; ssq[tid>>5] = sq; }
    __syncthreads();
    s  = ss[0] + ss[1] + ss[2] + ss[3];
    sq = ssq[0] + ssq[1] + ssq[2] + ssq[3];
    const float mu = s * (1.0f/512.0f);
    const float var = sq * (1.0f/512.0f) - mu*mu;
    const float rstd = rsqrtf(var + 1e-5f);
    const float4 gg = reinterpret_cast<const float4*>(g)[tid];
    const float4 bb = reinterpret_cast<const float4*>(b)[tid];
    float4 r;
    r.x = (v.x - mu)*rstd*gg.x + bb.x;
    r.y = (v.y - mu)*rstd*gg.y + bb.y;
    r.z = (v.z - mu)*rstd*gg.z + bb.z;
    r.w = (v.w - mu)*rstd*gg.w + bb.w;
    reinterpret_cast<float4*>(out + row*512)[tid] = r;
}

// ---------------- launch ------------------------------------------------------
extern "C" void kernel_launch(void* const* d_in, const int* in_sizes, int n_in,
                              void* d_out, int out_size)
{
    const float* x    = (const float*)d_in[0];
    const float* Wqkv = (const float*)d_in[1];
    const float* bqkv = (const float*)d_in[2];
    const float* Wout = (const float*)d_in[3];
    const float* bout = (const float*)d_in[4];
    const float* dl   = (const float*)d_in[5];
    const float* lng  = (const float*)d_in[6];
    const float* lnb  = (const float*)d_in[7];
    float* out = (float*)d_out;

    // shared memory sizes
    const size_t smemG = (size_t)(128*AH_LD + 32*BH_LD) * 2 * sizeof(__nv_bfloat16)
                       + (size_t)(8 * 32 * 64) * sizeof(float);   // 108544 B
    const size_t smem2 = (size_t)(2*128*65 + 129) * sizeof(float);
    const size_t smem4 = (size_t)(3*8320 + 128*132 + 64*65 + 64 + 129 + 128) * sizeof(float);

    cudaFuncSetAttribute(gemm_qkv_kernel,
        cudaFuncAttributeMaxDynamicSharedMemorySize, (int)smemG);
    cudaFuncSetAttribute(gemm_out_kernel,
        cudaFuncAttributeMaxDynamicSharedMemorySize, (int)smemG);
    cudaFuncSetAttribute(chunk_sum_kernel,
        cudaFuncAttributeMaxDynamicSharedMemorySize, (int)smem2);
    cudaFuncSetAttribute(attn_chunk_kernel,
        cudaFuncAttributeMaxDynamicSharedMemorySize, (int)smem4);

    gemm_qkv_kernel<<<dim3(12, 32), 256, smemG>>>(x, Wqkv, bqkv);
    chunk_sum_kernel<<<dim3(NCH, BHN), 256, smem2>>>(dl);
    scan_kernel<<<BHN, 256>>>(dl);
    attn_chunk_kernel<<<dim3(NCH, BHN), 256, smem4>>>(dl);
    gemm_out_kernel<<<dim3(4, 32), 256, smemG>>>(Wout, bout);
    ln_kernel<<<MM, 128>>>(lng, lnb, out);
}